// round 6
// baseline (speedup 1.0000x reference)
#include <cuda_runtime.h>
#include <cuda_bf16.h>
#include <math.h>
#include <stdint.h>

// ---------------------------------------------------------------------------
// Problem constants
// ---------------------------------------------------------------------------
#define NMAX 50000
#define EMAX 800000
#define F_IN 256
#define HDIM 128
#define DDIM 64
#define PDIM 512   // 8 projections x 64

// Packed projection offsets within a row of P.
#define OFF_QMU 0
#define OFF_SMU 64
#define OFF_QLS 128
#define OFF_SLS 192
#define OFF_KMU 256
#define OFF_VMU 320
#define OFF_KLS 384
#define OFF_VLS 448

// ---------------------------------------------------------------------------
// Static device scratch
// ---------------------------------------------------------------------------
__device__ int   g_is64;
__device__ int   g_cnt[NMAX];
__device__ int   g_pref[NMAX];
__device__ int   g_bsum[64];
__device__ int   g_rowptr[NMAX + 1];
__device__ int   g_cursor[NMAX];
__device__ int   g_src32[EMAX];
__device__ int   g_dst32[EMAX];
__device__ int   g_csr_src[EMAX];
__device__ float g_dinv[NMAX];
__device__ float g_h0[(size_t)NMAX * HDIM];
__device__ float g_h [(size_t)NMAX * HDIM];
__device__ float g_P [(size_t)NMAX * PDIM];
__device__ float g_Wcat[HDIM * PDIM];
__device__ float g_bcat[PDIM];

// ---------------------------------------------------------------------------
// Edge dtype detection
// ---------------------------------------------------------------------------
__global__ void detect_dtype_kernel(const int* __restrict__ w, int e) {
    __shared__ int s[256];
    int t = threadIdx.x;
    int limit = (e < 256) ? e : 256;
    int nz = 0;
    if (t < limit) nz = (w[2 * t + 1] != 0) ? 1 : 0;
    s[t] = nz;
    __syncthreads();
    for (int o = 128; o; o >>= 1) {
        if (t < o) s[t] += s[t + o];
        __syncthreads();
    }
    if (t == 0) g_is64 = (s[0] == 0) ? 1 : 0;
}

__global__ void zero_cnt_kernel(int n) {
    int i = blockIdx.x * blockDim.x + threadIdx.x;
    if (i < n) g_cnt[i] = 0;
}

__global__ void edge_prep_kernel(const void* __restrict__ ei, int e, int n) {
    int idx = blockIdx.x * blockDim.x + threadIdx.x;
    if (idx >= e) return;
    int s, d;
    if (g_is64) {
        const long long* p = (const long long*)ei;
        s = (int)p[idx];
        d = (int)p[idx + e];
    } else {
        const int* p = (const int*)ei;
        s = p[idx];
        d = p[idx + e];
    }
    s = (s < 0) ? 0 : ((s >= n) ? n - 1 : s);
    d = (d < 0) ? 0 : ((d >= n) ? n - 1 : d);
    g_src32[idx] = s;
    g_dst32[idx] = d;
    atomicAdd(&g_cnt[d], 1);
}

// ---------------------------------------------------------------------------
// Parallel scan (2 passes)
// ---------------------------------------------------------------------------
__global__ void scan_pass1_kernel(int n) {
    __shared__ int s[1024];
    int t = threadIdx.x;
    int i = blockIdx.x * 1024 + t;
    int v = (i < n) ? g_cnt[i] : 0;
    s[t] = v;
    __syncthreads();
    #pragma unroll
    for (int off = 1; off < 1024; off <<= 1) {
        int u = 0;
        if (t >= off) u = s[t - off];
        __syncthreads();
        if (t >= off) s[t] += u;
        __syncthreads();
    }
    if (i < n) g_pref[i] = s[t];
    if (t == 1023) g_bsum[blockIdx.x] = s[t];
}

__global__ void scan_pass2_kernel(int n) {
    __shared__ int sboff;
    int b = blockIdx.x;
    int t = threadIdx.x;
    if (t == 0) {
        int acc = 0;
        for (int j = 0; j < b; ++j) acc += g_bsum[j];
        sboff = acc;
    }
    __syncthreads();
    int i = b * 1024 + t;
    if (i < n) {
        int incl = g_pref[i] + sboff;
        int c = g_cnt[i];
        int excl = incl - c;
        g_rowptr[i] = excl;
        g_cursor[i] = excl;
        g_dinv[i] = rsqrtf((float)(c + 1));
        if (i == n - 1) g_rowptr[n] = incl;
    }
}

__global__ void fill_csr_kernel(int e) {
    int idx = blockIdx.x * blockDim.x + threadIdx.x;
    if (idx >= e) return;
    int d = g_dst32[idx];
    int pos = atomicAdd(&g_cursor[d], 1);
    g_csr_src[pos] = g_src32[idx];
}

// Pointer order matches packed offsets: qmu,smu,qls,sls,kmu,vmu,kls,vls
__global__ void pack_weights_kernel(
    const float* W0, const float* W1, const float* W2, const float* W3,
    const float* W4, const float* W5, const float* W6, const float* W7,
    const float* b0, const float* b1, const float* b2, const float* b3,
    const float* b4, const float* b5, const float* b6, const float* b7) {
    const float* Ws[8] = {W0, W1, W2, W3, W4, W5, W6, W7};
    const float* bs[8] = {b0, b1, b2, b3, b4, b5, b6, b7};
    int idx = blockIdx.x * blockDim.x + threadIdx.x;
    if (idx < HDIM * PDIM) {
        int k = idx / PDIM;
        int j = idx % PDIM;
        int p = j / DDIM;
        int c = j % DDIM;
        g_Wcat[idx] = Ws[p][k * DDIM + c];
    }
    if (idx < PDIM) {
        g_bcat[idx] = bs[idx / DDIM][idx % DDIM];
    }
}

// ---------------------------------------------------------------------------
// TF32 tensor-core GEMM v2: C[M,NC] = A[M,K] @ B[K,NC] (+bias)
// Block 128x128x32, 256 threads = 8 warps (2x4), warp tile 64x32.
// Fragment-packed smem (all LDS.64, conflict-free), conflict-free tile
// stores, register-prefetch pipeline.
// K % 32 == 0, NC % 128 == 0, M ragged.
// ---------------------------------------------------------------------------
#define TM 128
#define TN 128
#define TK 32
#define A_KSTRIDE 136    // words per k-row of As (128 + 8 pad)
#define B_KSBLOCK 1032   // words per 8-k block of Bs (128*8 + 8 pad)

__device__ __forceinline__ uint32_t f2tf32(float v) {
    uint32_t o;
    asm volatile("cvt.rna.tf32.f32 %0, %1;" : "=r"(o) : "f"(v));
    return o;
}

// As word offset: pairs (m, m+8) adjacent within each 16-row group.
__device__ __forceinline__ int a_off(int k, int m) {
    return k * A_KSTRIDE + ((((m >> 4) << 3) + (m & 7)) << 1) + ((m >> 3) & 1);
}
// Bs word offset: pairs (k, k+4) adjacent; k = ks*8 + khalf*4 + tg.
__device__ __forceinline__ int b_off(int k, int n) {
    return (k >> 3) * B_KSBLOCK + (n << 3) + ((k & 3) << 1) + ((k >> 2) & 1);
}

__device__ __forceinline__ void mma_tf32(float* c,
    uint32_t a0, uint32_t a1, uint32_t a2, uint32_t a3,
    uint32_t b0, uint32_t b1) {
    asm volatile(
        "mma.sync.aligned.m16n8k8.row.col.f32.tf32.tf32.f32 "
        "{%0,%1,%2,%3}, {%4,%5,%6,%7}, {%8,%9}, {%0,%1,%2,%3};"
        : "+f"(c[0]), "+f"(c[1]), "+f"(c[2]), "+f"(c[3])
        : "r"(a0), "r"(a1), "r"(a2), "r"(a3), "r"(b0), "r"(b1));
}

__device__ __forceinline__ void gemm_tf32_core(
    const float* __restrict__ A, const float* __restrict__ B,
    const float* __restrict__ bias, float* __restrict__ C,
    int M, int K, int NC) {
    __shared__ uint32_t As[TK * A_KSTRIDE];          // 4352 words
    __shared__ uint32_t Bs[(TK / 8) * B_KSBLOCK];    // 4128 words

    int t = threadIdx.x;
    int lane = t & 31;
    int warp = t >> 5;
    int wm = warp >> 2;        // 0..1
    int wn = warp & 3;         // 0..3
    int g  = lane >> 2;        // 0..7
    int tg = lane & 3;         // 0..3

    int rowBlock = blockIdx.y * TM;
    int colBlock = blockIdx.x * TN;

    float c[4][4][4];
    #pragma unroll
    for (int i = 0; i < 4; ++i)
        #pragma unroll
        for (int j = 0; j < 4; ++j)
            #pragma unroll
            for (int k = 0; k < 4; ++k) c[i][j][k] = 0.f;

    // Loader assignment (per l in 0..3):
    //   A: idx = t + 256l; am = idx & 127 (row), akq = idx >> 7 (k-quad 0..7)
    //   B: bk = idx & 31 (k-row), bnq = idx >> 5 (n-quad 0..31)
    float4 pa[4], pb[4];

    // prologue: load tile k0=0 into regs
    #pragma unroll
    for (int l = 0; l < 4; ++l) {
        int idx = t + l * 256;
        int am = idx & 127, akq = idx >> 7;
        int grow = rowBlock + am;
        pa[l] = (grow < M) ? *(const float4*)&A[(size_t)grow * K + akq * 4]
                           : make_float4(0.f, 0.f, 0.f, 0.f);
        int bk = idx & 31, bnq = idx >> 5;
        pb[l] = *(const float4*)&B[(size_t)bk * NC + colBlock + bnq * 4];
    }
    // store tile 0
    #pragma unroll
    for (int l = 0; l < 4; ++l) {
        int idx = t + l * 256;
        int am = idx & 127, akq = idx >> 7;
        int ak = akq * 4;
        As[a_off(ak + 0, am)] = f2tf32(pa[l].x);
        As[a_off(ak + 1, am)] = f2tf32(pa[l].y);
        As[a_off(ak + 2, am)] = f2tf32(pa[l].z);
        As[a_off(ak + 3, am)] = f2tf32(pa[l].w);
        int bk = idx & 31, bn = (idx >> 5) * 4;
        Bs[b_off(bk, bn + 0)] = f2tf32(pb[l].x);
        Bs[b_off(bk, bn + 1)] = f2tf32(pb[l].y);
        Bs[b_off(bk, bn + 2)] = f2tf32(pb[l].z);
        Bs[b_off(bk, bn + 3)] = f2tf32(pb[l].w);
    }
    __syncthreads();

    for (int k0 = TK; ; k0 += TK) {
        bool more = (k0 < K);
        if (more) {
            // prefetch next tile into registers (latency hidden by MMAs)
            #pragma unroll
            for (int l = 0; l < 4; ++l) {
                int idx = t + l * 256;
                int am = idx & 127, akq = idx >> 7;
                int grow = rowBlock + am;
                pa[l] = (grow < M)
                    ? *(const float4*)&A[(size_t)grow * K + k0 + akq * 4]
                    : make_float4(0.f, 0.f, 0.f, 0.f);
                int bk = idx & 31, bnq = idx >> 5;
                pb[l] = *(const float4*)&B[(size_t)(k0 + bk) * NC + colBlock + bnq * 4];
            }
        }

        // compute on current smem tile
        #pragma unroll
        for (int ks = 0; ks < 4; ++ks) {
            int kr = ks * 8 + tg;
            uint32_t a[4][4];
            uint32_t b[4][2];
            #pragma unroll
            for (int mt = 0; mt < 4; ++mt) {
                int base = kr * A_KSTRIDE + (((wm * 4 + mt) * 8 + g) << 1);
                uint2 p0 = *(const uint2*)&As[base];
                uint2 p1 = *(const uint2*)&As[base + 4 * A_KSTRIDE];
                a[mt][0] = p0.x; a[mt][1] = p0.y;
                a[mt][2] = p1.x; a[mt][3] = p1.y;
            }
            #pragma unroll
            for (int nt = 0; nt < 4; ++nt) {
                int nb = wn * 32 + nt * 8 + g;
                uint2 q = *(const uint2*)&Bs[ks * B_KSBLOCK + (nb << 3) + (tg << 1)];
                b[nt][0] = q.x; b[nt][1] = q.y;
            }
            #pragma unroll
            for (int mt = 0; mt < 4; ++mt)
                #pragma unroll
                for (int nt = 0; nt < 4; ++nt)
                    mma_tf32(c[mt][nt], a[mt][0], a[mt][1], a[mt][2], a[mt][3],
                             b[nt][0], b[nt][1]);
        }

        if (!more) break;
        __syncthreads();   // all warps done reading smem
        #pragma unroll
        for (int l = 0; l < 4; ++l) {
            int idx = t + l * 256;
            int am = idx & 127, akq = idx >> 7;
            int ak = akq * 4;
            As[a_off(ak + 0, am)] = f2tf32(pa[l].x);
            As[a_off(ak + 1, am)] = f2tf32(pa[l].y);
            As[a_off(ak + 2, am)] = f2tf32(pa[l].z);
            As[a_off(ak + 3, am)] = f2tf32(pa[l].w);
            int bk = idx & 31, bn = (idx >> 5) * 4;
            Bs[b_off(bk, bn + 0)] = f2tf32(pb[l].x);
            Bs[b_off(bk, bn + 1)] = f2tf32(pb[l].y);
            Bs[b_off(bk, bn + 2)] = f2tf32(pb[l].z);
            Bs[b_off(bk, bn + 3)] = f2tf32(pb[l].w);
        }
        __syncthreads();   // smem ready
    }

    // Epilogue (same mapping as validated R5 kernel)
    #pragma unroll
    for (int mt = 0; mt < 4; ++mt) {
        #pragma unroll
        for (int nt = 0; nt < 4; ++nt) {
            int col = colBlock + wn * 32 + nt * 8 + tg * 2;
            float b0 = 0.f, b1 = 0.f;
            if (bias) { b0 = bias[col]; b1 = bias[col + 1]; }
            int row0 = rowBlock + wm * 64 + mt * 16 + g;
            if (row0 < M) {
                float2 o = make_float2(c[mt][nt][0] + b0, c[mt][nt][1] + b1);
                *(float2*)&C[(size_t)row0 * NC + col] = o;
            }
            int row1 = row0 + 8;
            if (row1 < M) {
                float2 o = make_float2(c[mt][nt][2] + b0, c[mt][nt][3] + b1);
                *(float2*)&C[(size_t)row1 * NC + col] = o;
            }
        }
    }
}

__global__ __launch_bounds__(256) void gemm_xw_kernel(
    const float* __restrict__ A, const float* __restrict__ B, int M) {
    gemm_tf32_core(A, B, nullptr, g_h0, M, F_IN, HDIM);
}

__global__ __launch_bounds__(256) void gemm_proj_kernel(int M) {
    gemm_tf32_core(g_h, g_Wcat, g_bcat, g_P, M, HDIM, PDIM);
}

// ---------------------------------------------------------------------------
// GCN aggregate: one warp per node.
// ---------------------------------------------------------------------------
__global__ void gcn_agg_kernel(const float* __restrict__ bias, int n) {
    int warp = (blockIdx.x * blockDim.x + threadIdx.x) >> 5;
    int lane = threadIdx.x & 31;
    if (warp >= n) return;
    int i = warp;
    float di = g_dinv[i];

    float4 acc = make_float4(0.f, 0.f, 0.f, 0.f);
    int e0 = g_rowptr[i], e1 = g_rowptr[i + 1];
    for (int e = e0; e < e1; ++e) {
        int src = g_csr_src[e];
        float w = g_dinv[src] * di;
        float4 v = *(const float4*)&g_h0[(size_t)src * HDIM + lane * 4];
        acc.x = fmaf(w, v.x, acc.x);
        acc.y = fmaf(w, v.y, acc.y);
        acc.z = fmaf(w, v.z, acc.z);
        acc.w = fmaf(w, v.w, acc.w);
    }
    {   // self loop
        float w = di * di;
        float4 v = *(const float4*)&g_h0[(size_t)i * HDIM + lane * 4];
        acc.x = fmaf(w, v.x, acc.x);
        acc.y = fmaf(w, v.y, acc.y);
        acc.z = fmaf(w, v.z, acc.z);
        acc.w = fmaf(w, v.w, acc.w);
    }
    float4 bb = *(const float4*)&bias[lane * 4];
    acc.x += bb.x; acc.y += bb.y; acc.z += bb.z; acc.w += bb.w;
    acc.x = (acc.x >= 0.f) ? acc.x : 0.01f * acc.x;
    acc.y = (acc.y >= 0.f) ? acc.y : 0.01f * acc.y;
    acc.z = (acc.z >= 0.f) ? acc.z : 0.01f * acc.z;
    acc.w = (acc.w >= 0.f) ? acc.w : 0.01f * acc.w;
    *(float4*)&g_h[(size_t)i * HDIM + lane * 4] = acc;
}

// ---------------------------------------------------------------------------
// Fused TransformerConv (mu + logstd): one warp per dst node, online softmax.
// ---------------------------------------------------------------------------
__global__ void transformer_kernel(float* __restrict__ out, int n) {
    int warp = (blockIdx.x * blockDim.x + threadIdx.x) >> 5;
    int lane = threadIdx.x & 31;
    if (warp >= n) return;
    int i = warp;
    const float* Pi = &g_P[(size_t)i * PDIM];

    float qm0 = Pi[OFF_QMU + lane], qm1 = Pi[OFF_QMU + 32 + lane];
    float ql0 = Pi[OFF_QLS + lane], ql1 = Pi[OFF_QLS + 32 + lane];

    float mm = -INFINITY, ml = -INFINITY;
    float sm = 0.f, sl = 0.f;
    float am0 = 0.f, am1 = 0.f, al0 = 0.f, al1 = 0.f;

    int e0 = g_rowptr[i], e1 = g_rowptr[i + 1];
    for (int e = e0; e < e1; ++e) {
        int src = g_csr_src[e];
        const float* Ps = &g_P[(size_t)src * PDIM];

        float pm = qm0 * Ps[OFF_KMU + lane] + qm1 * Ps[OFF_KMU + 32 + lane];
        float pl = ql0 * Ps[OFF_KLS + lane] + ql1 * Ps[OFF_KLS + 32 + lane];
        #pragma unroll
        for (int off = 16; off; off >>= 1) {
            pm += __shfl_xor_sync(0xffffffffu, pm, off);
            pl += __shfl_xor_sync(0xffffffffu, pl, off);
        }
        float alm = pm * 0.125f;
        float all = pl * 0.125f;

        float vm0 = Ps[OFF_VMU + lane], vm1 = Ps[OFF_VMU + 32 + lane];
        float vl0 = Ps[OFF_VLS + lane], vl1 = Ps[OFF_VLS + 32 + lane];

        {
            float nm = fmaxf(mm, alm);
            float scale = __expf(mm - nm);
            float p = __expf(alm - nm);
            sm = sm * scale + p;
            am0 = am0 * scale + p * vm0;
            am1 = am1 * scale + p * vm1;
            mm = nm;
        }
        {
            float nm = fmaxf(ml, all);
            float scale = __expf(ml - nm);
            float p = __expf(all - nm);
            sl = sl * scale + p;
            al0 = al0 * scale + p * vl0;
            al1 = al1 * scale + p * vl1;
            ml = nm;
        }
    }

    size_t nd = (size_t)n * DDIM;
    float om0 = am0 / (sm + 1e-16f) + Pi[OFF_SMU + lane];
    float om1 = am1 / (sm + 1e-16f) + Pi[OFF_SMU + 32 + lane];
    out[(size_t)i * DDIM + lane]      = om0;
    out[(size_t)i * DDIM + 32 + lane] = om1;

    float ol0 = fminf(al0 / (sl + 1e-16f) + Pi[OFF_SLS + lane], 10.0f);
    float ol1 = fminf(al1 / (sl + 1e-16f) + Pi[OFF_SLS + 32 + lane], 10.0f);
    out[nd + (size_t)i * DDIM + lane]      = ol0;
    out[nd + (size_t)i * DDIM + 32 + lane] = ol1;
}

// ---------------------------------------------------------------------------
// Launch
// ---------------------------------------------------------------------------
extern "C" void kernel_launch(void* const* d_in, const int* in_sizes, int n_in,
                              void* d_out, int out_size) {
    const float* x     = (const float*)d_in[0];
    const void*  ei    = (const void*)d_in[1];
    const float* W_gcn = (const float*)d_in[2];
    const float* b_gcn = (const float*)d_in[3];
    const float* Wq_mu = (const float*)d_in[4];  const float* bq_mu = (const float*)d_in[5];
    const float* Wk_mu = (const float*)d_in[6];  const float* bk_mu = (const float*)d_in[7];
    const float* Wv_mu = (const float*)d_in[8];  const float* bv_mu = (const float*)d_in[9];
    const float* Ws_mu = (const float*)d_in[10]; const float* bs_mu = (const float*)d_in[11];
    const float* Wq_ls = (const float*)d_in[12]; const float* bq_ls = (const float*)d_in[13];
    const float* Wk_ls = (const float*)d_in[14]; const float* bk_ls = (const float*)d_in[15];
    const float* Wv_ls = (const float*)d_in[16]; const float* bv_ls = (const float*)d_in[17];
    const float* Ws_ls = (const float*)d_in[18]; const float* bs_ls = (const float*)d_in[19];
    float* out = (float*)d_out;

    int n = in_sizes[0] / F_IN;      // 50000
    int e = in_sizes[1] / 2;         // 800000

    // 0) dtype detect
    detect_dtype_kernel<<<1, 256>>>((const int*)ei, e);

    // 1) CSR build
    zero_cnt_kernel<<<(n + 255) / 256, 256>>>(n);
    edge_prep_kernel<<<(e + 255) / 256, 256>>>(ei, e, n);
    int nblk = (n + 1023) / 1024;
    scan_pass1_kernel<<<nblk, 1024>>>(n);
    scan_pass2_kernel<<<nblk, 1024>>>(n);
    fill_csr_kernel<<<(e + 255) / 256, 256>>>(e);

    // 2) Pack projection weights (qmu,smu,qls,sls,kmu,vmu,kls,vls)
    pack_weights_kernel<<<(HDIM * PDIM + 255) / 256, 256>>>(
        Wq_mu, Ws_mu, Wq_ls, Ws_ls, Wk_mu, Wv_mu, Wk_ls, Wv_ls,
        bq_mu, bs_mu, bq_ls, bs_ls, bk_mu, bv_mu, bk_ls, bv_ls);

    // 3) h0 = x @ W_gcn    [n,256]@[256,128]  (tf32 MMA)
    {
        dim3 grid(HDIM / TN, (n + TM - 1) / TM);
        gemm_xw_kernel<<<grid, 256>>>(x, W_gcn, n);
    }

    // 4) GCN aggregate + bias + LeakyReLU -> h
    gcn_agg_kernel<<<(n + 7) / 8, 256>>>(b_gcn, n);

    // 5) P = h @ Wcat + bcat    [n,128]@[128,512]  (tf32 MMA)
    {
        dim3 grid(PDIM / TN, (n + TM - 1) / TM);
        gemm_proj_kernel<<<grid, 256>>>(n);
    }

    // 6) Fused TransformerConv (mu + logstd) -> out
    transformer_kernel<<<(n + 7) / 8, 256>>>(out, n);
}

// round 7
// speedup vs baseline: 1.0963x; 1.0963x over previous
#include <cuda_runtime.h>
#include <cuda_bf16.h>
#include <math.h>
#include <stdint.h>

// ---------------------------------------------------------------------------
// Problem constants
// ---------------------------------------------------------------------------
#define NMAX 50000
#define EMAX 800000
#define F_IN 256
#define HDIM 128
#define DDIM 64
#define PDIM 512   // 8 projections x 64

// Packed projection offsets within a row of P.
#define OFF_QMU 0
#define OFF_SMU 64
#define OFF_QLS 128
#define OFF_SLS 192
#define OFF_KMU 256
#define OFF_VMU 320
#define OFF_KLS 384
#define OFF_VLS 448

// ---------------------------------------------------------------------------
// Static device scratch
// ---------------------------------------------------------------------------
__device__ int      g_is64;
__device__ int      g_cnt[NMAX];
__device__ int      g_pref[NMAX];
__device__ int      g_bsum[64];
__device__ int      g_rowptr[NMAX + 1];
__device__ int      g_cursor[NMAX];
__device__ int      g_src32[EMAX];
__device__ int      g_dst32[EMAX];
__device__ int      g_csr_src[EMAX];
__device__ float    g_dinv[NMAX];
__device__ uint32_t g_xA [(size_t)NMAX * F_IN];   // x as tf32 bits
__device__ uint32_t g_WgB[F_IN * HDIM];           // W_gcn as tf32 bits
__device__ float    g_h0 [(size_t)NMAX * HDIM];   // x @ W_gcn (fp32)
__device__ uint32_t g_h  [(size_t)NMAX * HDIM];   // leaky(agg)+b, tf32 bits
__device__ float    g_P  [(size_t)NMAX * PDIM];   // packed projections (fp32)
__device__ uint32_t g_Wcat[HDIM * PDIM];          // tf32 bits
__device__ float    g_bcat[PDIM];

__device__ __forceinline__ uint32_t f2tf32(float v) {
    uint32_t o;
    asm volatile("cvt.rna.tf32.f32 %0, %1;" : "=r"(o) : "f"(v));
    return o;
}

// ---------------------------------------------------------------------------
// Edge dtype detection
// ---------------------------------------------------------------------------
__global__ void detect_dtype_kernel(const int* __restrict__ w, int e) {
    __shared__ int s[256];
    int t = threadIdx.x;
    int limit = (e < 256) ? e : 256;
    int nz = 0;
    if (t < limit) nz = (w[2 * t + 1] != 0) ? 1 : 0;
    s[t] = nz;
    __syncthreads();
    for (int o = 128; o; o >>= 1) {
        if (t < o) s[t] += s[t + o];
        __syncthreads();
    }
    if (t == 0) g_is64 = (s[0] == 0) ? 1 : 0;
}

__global__ void zero_cnt_kernel(int n) {
    int i = blockIdx.x * blockDim.x + threadIdx.x;
    if (i < n) g_cnt[i] = 0;
}

__global__ void edge_prep_kernel(const void* __restrict__ ei, int e, int n) {
    int idx = blockIdx.x * blockDim.x + threadIdx.x;
    if (idx >= e) return;
    int s, d;
    if (g_is64) {
        const long long* p = (const long long*)ei;
        s = (int)p[idx];
        d = (int)p[idx + e];
    } else {
        const int* p = (const int*)ei;
        s = p[idx];
        d = p[idx + e];
    }
    s = (s < 0) ? 0 : ((s >= n) ? n - 1 : s);
    d = (d < 0) ? 0 : ((d >= n) ? n - 1 : d);
    g_src32[idx] = s;
    g_dst32[idx] = d;
    atomicAdd(&g_cnt[d], 1);
}

// ---------------------------------------------------------------------------
// Parallel scan (2 passes)
// ---------------------------------------------------------------------------
__global__ void scan_pass1_kernel(int n) {
    __shared__ int s[1024];
    int t = threadIdx.x;
    int i = blockIdx.x * 1024 + t;
    int v = (i < n) ? g_cnt[i] : 0;
    s[t] = v;
    __syncthreads();
    #pragma unroll
    for (int off = 1; off < 1024; off <<= 1) {
        int u = 0;
        if (t >= off) u = s[t - off];
        __syncthreads();
        if (t >= off) s[t] += u;
        __syncthreads();
    }
    if (i < n) g_pref[i] = s[t];
    if (t == 1023) g_bsum[blockIdx.x] = s[t];
}

__global__ void scan_pass2_kernel(int n) {
    __shared__ int sboff;
    int b = blockIdx.x;
    int t = threadIdx.x;
    if (t == 0) {
        int acc = 0;
        for (int j = 0; j < b; ++j) acc += g_bsum[j];
        sboff = acc;
    }
    __syncthreads();
    int i = b * 1024 + t;
    if (i < n) {
        int incl = g_pref[i] + sboff;
        int c = g_cnt[i];
        int excl = incl - c;
        g_rowptr[i] = excl;
        g_cursor[i] = excl;
        g_dinv[i] = rsqrtf((float)(c + 1));
        if (i == n - 1) g_rowptr[n] = incl;
    }
}

__global__ void fill_csr_kernel(int e) {
    int idx = blockIdx.x * blockDim.x + threadIdx.x;
    if (idx >= e) return;
    int d = g_dst32[idx];
    int pos = atomicAdd(&g_cursor[d], 1);
    g_csr_src[pos] = g_src32[idx];
}

// ---------------------------------------------------------------------------
// tf32 pre-conversion of GEMM inputs
// ---------------------------------------------------------------------------
__global__ void cvt_x_kernel(const float4* __restrict__ in, int n4) {
    int i = blockIdx.x * blockDim.x + threadIdx.x;
    if (i >= n4) return;
    float4 v = in[i];
    uint4 u;
    u.x = f2tf32(v.x); u.y = f2tf32(v.y);
    u.z = f2tf32(v.z); u.w = f2tf32(v.w);
    ((uint4*)g_xA)[i] = u;
}

__global__ void cvt_wg_kernel(const float4* __restrict__ in, int n4) {
    int i = blockIdx.x * blockDim.x + threadIdx.x;
    if (i >= n4) return;
    float4 v = in[i];
    uint4 u;
    u.x = f2tf32(v.x); u.y = f2tf32(v.y);
    u.z = f2tf32(v.z); u.w = f2tf32(v.w);
    ((uint4*)g_WgB)[i] = u;
}

// Pointer order matches packed offsets: qmu,smu,qls,sls,kmu,vmu,kls,vls
__global__ void pack_weights_kernel(
    const float* W0, const float* W1, const float* W2, const float* W3,
    const float* W4, const float* W5, const float* W6, const float* W7,
    const float* b0, const float* b1, const float* b2, const float* b3,
    const float* b4, const float* b5, const float* b6, const float* b7) {
    const float* Ws[8] = {W0, W1, W2, W3, W4, W5, W6, W7};
    const float* bs[8] = {b0, b1, b2, b3, b4, b5, b6, b7};
    int idx = blockIdx.x * blockDim.x + threadIdx.x;
    if (idx < HDIM * PDIM) {
        int k = idx / PDIM;
        int j = idx % PDIM;
        int p = j / DDIM;
        int c = j % DDIM;
        g_Wcat[idx] = f2tf32(Ws[p][k * DDIM + c]);
    }
    if (idx < PDIM) {
        g_bcat[idx] = bs[idx / DDIM][idx % DDIM];
    }
}

// ---------------------------------------------------------------------------
// TF32 tensor-core GEMM v3: inputs are pre-converted tf32 bits.
// Block 128x128x32, 256 threads = 8 warps (2x4), warp tile 64x32.
// R5-proven fragment mapping; A-store made conflict-free via lane-consecutive
// row mapping; zero cvt inside the kernel.
// ---------------------------------------------------------------------------
#define TM 128
#define TN 128
#define TK 32
#define SROW 136   // 128 + 8 pad words

__device__ __forceinline__ void mma_tf32(float* c,
    uint32_t a0, uint32_t a1, uint32_t a2, uint32_t a3,
    uint32_t b0, uint32_t b1) {
    asm volatile(
        "mma.sync.aligned.m16n8k8.row.col.f32.tf32.tf32.f32 "
        "{%0,%1,%2,%3}, {%4,%5,%6,%7}, {%8,%9}, {%0,%1,%2,%3};"
        : "+f"(c[0]), "+f"(c[1]), "+f"(c[2]), "+f"(c[3])
        : "r"(a0), "r"(a1), "r"(a2), "r"(a3), "r"(b0), "r"(b1));
}

__device__ __forceinline__ void gemm_tf32_core(
    const uint32_t* __restrict__ A, const uint32_t* __restrict__ B,
    const float* __restrict__ bias, float* __restrict__ C,
    int M, int K, int NC) {
    __shared__ uint32_t As[TK][SROW];   // As[k][m]
    __shared__ uint32_t Bs[TK][SROW];   // Bs[k][n]

    int t = threadIdx.x;
    int lane = t & 31;
    int warp = t >> 5;
    int wm = warp >> 2;        // 0..1
    int wn = warp & 3;         // 0..3
    int g  = lane >> 2;        // 0..7
    int tg = lane & 3;         // 0..3

    int rowBlock = blockIdx.y * TM;
    int colBlock = blockIdx.x * TN;

    float c[4][4][4];
    #pragma unroll
    for (int i = 0; i < 4; ++i)
        #pragma unroll
        for (int j = 0; j < 4; ++j)
            #pragma unroll
            for (int k = 0; k < 4; ++k) c[i][j][k] = 0.f;

    for (int k0 = 0; k0 < K; k0 += TK) {
        // A tile: am = idx&127 (lane-consecutive rows -> conflict-free STS),
        // akq = idx>>7 picks the k-quad.
        #pragma unroll
        for (int l = 0; l < 4; ++l) {
            int idx = t + l * 256;
            int am = idx & 127;
            int akq = idx >> 7;
            int ak = akq << 2;
            uint4 v = make_uint4(0u, 0u, 0u, 0u);
            int grow = rowBlock + am;
            if (grow < M)
                v = *(const uint4*)&A[(size_t)grow * K + k0 + ak];
            As[ak + 0][am] = v.x;
            As[ak + 1][am] = v.y;
            As[ak + 2][am] = v.z;
            As[ak + 3][am] = v.w;
        }
        // B tile: coalesced rows, STS.128 (2-way phase conflict, acceptable)
        #pragma unroll
        for (int l = 0; l < 4; ++l) {
            int idx = t + l * 256;
            int br = idx >> 5;            // 0..31
            int bc = (idx & 31) << 2;     // 0..124
            *(uint4*)&Bs[br][bc] =
                *(const uint4*)&B[(size_t)(k0 + br) * NC + colBlock + bc];
        }
        __syncthreads();

        #pragma unroll
        for (int ks = 0; ks < 4; ++ks) {
            int kr = ks * 8 + tg;
            uint32_t a[4][4], b[4][2];
            #pragma unroll
            for (int mt = 0; mt < 4; ++mt) {
                int mb = wm * 64 + mt * 16 + g;
                a[mt][0] = As[kr][mb];
                a[mt][1] = As[kr][mb + 8];
                a[mt][2] = As[kr + 4][mb];
                a[mt][3] = As[kr + 4][mb + 8];
            }
            #pragma unroll
            for (int nt = 0; nt < 4; ++nt) {
                int nb = wn * 32 + nt * 8 + g;
                b[nt][0] = Bs[kr][nb];
                b[nt][1] = Bs[kr + 4][nb];
            }
            #pragma unroll
            for (int mt = 0; mt < 4; ++mt)
                #pragma unroll
                for (int nt = 0; nt < 4; ++nt)
                    mma_tf32(c[mt][nt], a[mt][0], a[mt][1], a[mt][2], a[mt][3],
                             b[nt][0], b[nt][1]);
        }
        __syncthreads();
    }

    // Epilogue (validated mapping)
    #pragma unroll
    for (int mt = 0; mt < 4; ++mt) {
        #pragma unroll
        for (int nt = 0; nt < 4; ++nt) {
            int col = colBlock + wn * 32 + nt * 8 + tg * 2;
            float b0 = 0.f, b1 = 0.f;
            if (bias) { b0 = bias[col]; b1 = bias[col + 1]; }
            int row0 = rowBlock + wm * 64 + mt * 16 + g;
            if (row0 < M) {
                float2 o = make_float2(c[mt][nt][0] + b0, c[mt][nt][1] + b1);
                *(float2*)&C[(size_t)row0 * NC + col] = o;
            }
            int row1 = row0 + 8;
            if (row1 < M) {
                float2 o = make_float2(c[mt][nt][2] + b0, c[mt][nt][3] + b1);
                *(float2*)&C[(size_t)row1 * NC + col] = o;
            }
        }
    }
}

__global__ __launch_bounds__(256) void gemm_xw_kernel(int M) {
    gemm_tf32_core(g_xA, g_WgB, nullptr, g_h0, M, F_IN, HDIM);
}

__global__ __launch_bounds__(256) void gemm_proj_kernel(int M) {
    gemm_tf32_core(g_h, g_Wcat, g_bcat, g_P, M, HDIM, PDIM);
}

// ---------------------------------------------------------------------------
// GCN aggregate: one warp per node. Emits tf32-rounded h (GEMM would round
// identically, so numerics are unchanged).
// ---------------------------------------------------------------------------
__global__ void gcn_agg_kernel(const float* __restrict__ bias, int n) {
    int warp = (blockIdx.x * blockDim.x + threadIdx.x) >> 5;
    int lane = threadIdx.x & 31;
    if (warp >= n) return;
    int i = warp;
    float di = g_dinv[i];

    float4 acc = make_float4(0.f, 0.f, 0.f, 0.f);
    int e0 = g_rowptr[i], e1 = g_rowptr[i + 1];
    for (int e = e0; e < e1; ++e) {
        int src = g_csr_src[e];
        float w = g_dinv[src] * di;
        float4 v = *(const float4*)&g_h0[(size_t)src * HDIM + lane * 4];
        acc.x = fmaf(w, v.x, acc.x);
        acc.y = fmaf(w, v.y, acc.y);
        acc.z = fmaf(w, v.z, acc.z);
        acc.w = fmaf(w, v.w, acc.w);
    }
    {   // self loop
        float w = di * di;
        float4 v = *(const float4*)&g_h0[(size_t)i * HDIM + lane * 4];
        acc.x = fmaf(w, v.x, acc.x);
        acc.y = fmaf(w, v.y, acc.y);
        acc.z = fmaf(w, v.z, acc.z);
        acc.w = fmaf(w, v.w, acc.w);
    }
    float4 bb = *(const float4*)&bias[lane * 4];
    acc.x += bb.x; acc.y += bb.y; acc.z += bb.z; acc.w += bb.w;
    acc.x = (acc.x >= 0.f) ? acc.x : 0.01f * acc.x;
    acc.y = (acc.y >= 0.f) ? acc.y : 0.01f * acc.y;
    acc.z = (acc.z >= 0.f) ? acc.z : 0.01f * acc.z;
    acc.w = (acc.w >= 0.f) ? acc.w : 0.01f * acc.w;
    uint4 o;
    o.x = f2tf32(acc.x); o.y = f2tf32(acc.y);
    o.z = f2tf32(acc.z); o.w = f2tf32(acc.w);
    *(uint4*)&g_h[(size_t)i * HDIM + lane * 4] = o;
}

// ---------------------------------------------------------------------------
// Fused TransformerConv (mu + logstd): one warp per dst node, online softmax.
// ---------------------------------------------------------------------------
__global__ void transformer_kernel(float* __restrict__ out, int n) {
    int warp = (blockIdx.x * blockDim.x + threadIdx.x) >> 5;
    int lane = threadIdx.x & 31;
    if (warp >= n) return;
    int i = warp;
    const float* Pi = &g_P[(size_t)i * PDIM];

    float qm0 = Pi[OFF_QMU + lane], qm1 = Pi[OFF_QMU + 32 + lane];
    float ql0 = Pi[OFF_QLS + lane], ql1 = Pi[OFF_QLS + 32 + lane];

    float mm = -INFINITY, ml = -INFINITY;
    float sm = 0.f, sl = 0.f;
    float am0 = 0.f, am1 = 0.f, al0 = 0.f, al1 = 0.f;

    int e0 = g_rowptr[i], e1 = g_rowptr[i + 1];
    for (int e = e0; e < e1; ++e) {
        int src = g_csr_src[e];
        const float* Ps = &g_P[(size_t)src * PDIM];

        float pm = qm0 * Ps[OFF_KMU + lane] + qm1 * Ps[OFF_KMU + 32 + lane];
        float pl = ql0 * Ps[OFF_KLS + lane] + ql1 * Ps[OFF_KLS + 32 + lane];
        #pragma unroll
        for (int off = 16; off; off >>= 1) {
            pm += __shfl_xor_sync(0xffffffffu, pm, off);
            pl += __shfl_xor_sync(0xffffffffu, pl, off);
        }
        float alm = pm * 0.125f;
        float all = pl * 0.125f;

        float vm0 = Ps[OFF_VMU + lane], vm1 = Ps[OFF_VMU + 32 + lane];
        float vl0 = Ps[OFF_VLS + lane], vl1 = Ps[OFF_VLS + 32 + lane];

        {
            float nm = fmaxf(mm, alm);
            float scale = __expf(mm - nm);
            float p = __expf(alm - nm);
            sm = sm * scale + p;
            am0 = am0 * scale + p * vm0;
            am1 = am1 * scale + p * vm1;
            mm = nm;
        }
        {
            float nm = fmaxf(ml, all);
            float scale = __expf(ml - nm);
            float p = __expf(all - nm);
            sl = sl * scale + p;
            al0 = al0 * scale + p * vl0;
            al1 = al1 * scale + p * vl1;
            ml = nm;
        }
    }

    size_t nd = (size_t)n * DDIM;
    float om0 = am0 / (sm + 1e-16f) + Pi[OFF_SMU + lane];
    float om1 = am1 / (sm + 1e-16f) + Pi[OFF_SMU + 32 + lane];
    out[(size_t)i * DDIM + lane]      = om0;
    out[(size_t)i * DDIM + 32 + lane] = om1;

    float ol0 = fminf(al0 / (sl + 1e-16f) + Pi[OFF_SLS + lane], 10.0f);
    float ol1 = fminf(al1 / (sl + 1e-16f) + Pi[OFF_SLS + 32 + lane], 10.0f);
    out[nd + (size_t)i * DDIM + lane]      = ol0;
    out[nd + (size_t)i * DDIM + 32 + lane] = ol1;
}

// ---------------------------------------------------------------------------
// Launch
// ---------------------------------------------------------------------------
extern "C" void kernel_launch(void* const* d_in, const int* in_sizes, int n_in,
                              void* d_out, int out_size) {
    const float* x     = (const float*)d_in[0];
    const void*  ei    = (const void*)d_in[1];
    const float* W_gcn = (const float*)d_in[2];
    const float* b_gcn = (const float*)d_in[3];
    const float* Wq_mu = (const float*)d_in[4];  const float* bq_mu = (const float*)d_in[5];
    const float* Wk_mu = (const float*)d_in[6];  const float* bk_mu = (const float*)d_in[7];
    const float* Wv_mu = (const float*)d_in[8];  const float* bv_mu = (const float*)d_in[9];
    const float* Ws_mu = (const float*)d_in[10]; const float* bs_mu = (const float*)d_in[11];
    const float* Wq_ls = (const float*)d_in[12]; const float* bq_ls = (const float*)d_in[13];
    const float* Wk_ls = (const float*)d_in[14]; const float* bk_ls = (const float*)d_in[15];
    const float* Wv_ls = (const float*)d_in[16]; const float* bv_ls = (const float*)d_in[17];
    const float* Ws_ls = (const float*)d_in[18]; const float* bs_ls = (const float*)d_in[19];
    float* out = (float*)d_out;

    int n = in_sizes[0] / F_IN;      // 50000
    int e = in_sizes[1] / 2;         // 800000

    // 0) dtype detect
    detect_dtype_kernel<<<1, 256>>>((const int*)ei, e);

    // 1) CSR build
    zero_cnt_kernel<<<(n + 255) / 256, 256>>>(n);
    edge_prep_kernel<<<(e + 255) / 256, 256>>>(ei, e, n);
    int nblk = (n + 1023) / 1024;
    scan_pass1_kernel<<<nblk, 1024>>>(n);
    scan_pass2_kernel<<<nblk, 1024>>>(n);
    fill_csr_kernel<<<(e + 255) / 256, 256>>>(e);

    // 2) Pre-convert GEMM inputs to tf32 bits
    {
        int n4 = n * F_IN / 4;
        cvt_x_kernel<<<(n4 + 255) / 256, 256>>>((const float4*)x, n4);
        int w4 = F_IN * HDIM / 4;
        cvt_wg_kernel<<<(w4 + 255) / 256, 256>>>((const float4*)W_gcn, w4);
    }
    pack_weights_kernel<<<(HDIM * PDIM + 255) / 256, 256>>>(
        Wq_mu, Ws_mu, Wq_ls, Ws_ls, Wk_mu, Wv_mu, Wk_ls, Wv_ls,
        bq_mu, bs_mu, bq_ls, bs_ls, bk_mu, bv_mu, bk_ls, bv_ls);

    // 3) h0 = x @ W_gcn    [n,256]@[256,128]  (tf32 MMA)
    {
        dim3 grid(HDIM / TN, (n + TM - 1) / TM);
        gemm_xw_kernel<<<grid, 256>>>(n);
    }

    // 4) GCN aggregate + bias + LeakyReLU -> h (tf32 bits)
    gcn_agg_kernel<<<(n + 7) / 8, 256>>>(b_gcn, n);

    // 5) P = h @ Wcat + bcat    [n,128]@[128,512]  (tf32 MMA)
    {
        dim3 grid(PDIM / TN, (n + TM - 1) / TM);
        gemm_proj_kernel<<<grid, 256>>>(n);
    }

    // 6) Fused TransformerConv (mu + logstd) -> out
    transformer_kernel<<<(n + 7) / 8, 256>>>(out, n);
}

// round 9
// speedup vs baseline: 1.3285x; 1.2117x over previous
#include <cuda_runtime.h>
#include <cuda_bf16.h>
#include <math.h>
#include <stdint.h>

// ---------------------------------------------------------------------------
// Problem constants
// ---------------------------------------------------------------------------
#define NMAX 50000
#define EMAX 800000
#define F_IN 256
#define HDIM 128
#define DDIM 64
#define PDIM 512   // 8 projections x 64

// Packed projection block offsets within a row of P.
// Within each 64-dim block, dim c lives at position 2*(c%32) + (c/32):
// lane l reads the float2 at word 2l = dims (l, l+32).
#define OFF_QMU 0
#define OFF_SMU 64
#define OFF_QLS 128
#define OFF_SLS 192
#define OFF_KMU 256
#define OFF_VMU 320
#define OFF_KLS 384
#define OFF_VLS 448

// ---------------------------------------------------------------------------
// Static device scratch
// ---------------------------------------------------------------------------
__device__ int   g_is64;
__device__ int   g_cnt[NMAX];
__device__ int   g_pref[NMAX];
__device__ int   g_bsum[64];
__device__ int   g_rowptr[NMAX + 1];
__device__ int   g_cursor[NMAX];
__device__ int   g_src32[EMAX];
__device__ int   g_dst32[EMAX];
__device__ int   g_csr_src[EMAX];
__device__ float g_dinv[NMAX];
__device__ float g_h0[(size_t)NMAX * HDIM];   // x @ W_gcn
__device__ float g_h [(size_t)NMAX * HDIM];   // after agg + bias + leaky
__device__ float g_P [(size_t)NMAX * PDIM];   // packed projections (interleaved)
__device__ float g_Wcat[HDIM * PDIM];
__device__ float g_bcat[PDIM];

// ---------------------------------------------------------------------------
// Edge dtype detection
// ---------------------------------------------------------------------------
__global__ void detect_dtype_kernel(const int* __restrict__ w, int e) {
    __shared__ int s[256];
    int t = threadIdx.x;
    int limit = (e < 256) ? e : 256;
    int nz = 0;
    if (t < limit) nz = (w[2 * t + 1] != 0) ? 1 : 0;
    s[t] = nz;
    __syncthreads();
    for (int o = 128; o; o >>= 1) {
        if (t < o) s[t] += s[t + o];
        __syncthreads();
    }
    if (t == 0) g_is64 = (s[0] == 0) ? 1 : 0;
}

__global__ void zero_cnt_kernel(int n) {
    int i = blockIdx.x * blockDim.x + threadIdx.x;
    if (i < n) g_cnt[i] = 0;
}

__global__ void edge_prep_kernel(const void* __restrict__ ei, int e, int n) {
    int idx = blockIdx.x * blockDim.x + threadIdx.x;
    if (idx >= e) return;
    int s, d;
    if (g_is64) {
        const long long* p = (const long long*)ei;
        s = (int)p[idx];
        d = (int)p[idx + e];
    } else {
        const int* p = (const int*)ei;
        s = p[idx];
        d = p[idx + e];
    }
    s = (s < 0) ? 0 : ((s >= n) ? n - 1 : s);
    d = (d < 0) ? 0 : ((d >= n) ? n - 1 : d);
    g_src32[idx] = s;
    g_dst32[idx] = d;
    atomicAdd(&g_cnt[d], 1);
}

// ---------------------------------------------------------------------------
// Parallel scan (2 passes)
// ---------------------------------------------------------------------------
__global__ void scan_pass1_kernel(int n) {
    __shared__ int s[1024];
    int t = threadIdx.x;
    int i = blockIdx.x * 1024 + t;
    int v = (i < n) ? g_cnt[i] : 0;
    s[t] = v;
    __syncthreads();
    #pragma unroll
    for (int off = 1; off < 1024; off <<= 1) {
        int u = 0;
        if (t >= off) u = s[t - off];
        __syncthreads();
        if (t >= off) s[t] += u;
        __syncthreads();
    }
    if (i < n) g_pref[i] = s[t];
    if (t == 1023) g_bsum[blockIdx.x] = s[t];
}

__global__ void scan_pass2_kernel(int n) {
    __shared__ int sboff;
    int b = blockIdx.x;
    int t = threadIdx.x;
    if (t == 0) {
        int acc = 0;
        for (int j = 0; j < b; ++j) acc += g_bsum[j];
        sboff = acc;
    }
    __syncthreads();
    int i = b * 1024 + t;
    if (i < n) {
        int incl = g_pref[i] + sboff;
        int c = g_cnt[i];
        int excl = incl - c;
        g_rowptr[i] = excl;
        g_cursor[i] = excl;
        g_dinv[i] = rsqrtf((float)(c + 1));
        if (i == n - 1) g_rowptr[n] = incl;
    }
}

__global__ void fill_csr_kernel(int e) {
    int idx = blockIdx.x * blockDim.x + threadIdx.x;
    if (idx >= e) return;
    int d = g_dst32[idx];
    int pos = atomicAdd(&g_cursor[d], 1);
    g_csr_src[pos] = g_src32[idx];
}

// Pointer order matches packed offsets: qmu,smu,qls,sls,kmu,vmu,kls,vls.
// Within each 64-wide block, packed position cp holds original col
// c = (cp>>1) + 32*(cp&1).
__global__ void pack_weights_kernel(
    const float* W0, const float* W1, const float* W2, const float* W3,
    const float* W4, const float* W5, const float* W6, const float* W7,
    const float* b0, const float* b1, const float* b2, const float* b3,
    const float* b4, const float* b5, const float* b6, const float* b7) {
    const float* Ws[8] = {W0, W1, W2, W3, W4, W5, W6, W7};
    const float* bs[8] = {b0, b1, b2, b3, b4, b5, b6, b7};
    int idx = blockIdx.x * blockDim.x + threadIdx.x;
    if (idx < HDIM * PDIM) {
        int k = idx / PDIM;
        int j = idx % PDIM;
        int p = j / DDIM;
        int cp = j % DDIM;
        int c = (cp >> 1) + 32 * (cp & 1);
        g_Wcat[idx] = Ws[p][k * DDIM + c];
    }
    if (idx < PDIM) {
        int p = idx / DDIM;
        int cp = idx % DDIM;
        int c = (cp >> 1) + 32 * (cp & 1);
        g_bcat[idx] = bs[p][c];
    }
}

// ---------------------------------------------------------------------------
// TF32 tensor-core GEMM (exact R5 engine — proven): C = A @ B (+bias)
// Block 128x128x32, 256 threads = 8 warps (2x4), warp tile 64x32.
// ---------------------------------------------------------------------------
#define TM 128
#define TN 128
#define TK 32
#define SROW 136

__device__ __forceinline__ uint32_t f2tf32(float v) {
    uint32_t o;
    asm volatile("cvt.rna.tf32.f32 %0, %1;" : "=r"(o) : "f"(v));
    return o;
}

__device__ __forceinline__ void mma_tf32(float* c,
    uint32_t a0, uint32_t a1, uint32_t a2, uint32_t a3,
    uint32_t b0, uint32_t b1) {
    asm volatile(
        "mma.sync.aligned.m16n8k8.row.col.f32.tf32.tf32.f32 "
        "{%0,%1,%2,%3}, {%4,%5,%6,%7}, {%8,%9}, {%0,%1,%2,%3};"
        : "+f"(c[0]), "+f"(c[1]), "+f"(c[2]), "+f"(c[3])
        : "r"(a0), "r"(a1), "r"(a2), "r"(a3), "r"(b0), "r"(b1));
}

__device__ __forceinline__ void gemm_tf32_core(
    const float* __restrict__ A, const float* __restrict__ B,
    const float* __restrict__ bias, float* __restrict__ C,
    int M, int K, int NC) {
    __shared__ uint32_t As[TK][SROW];   // As[k][m]
    __shared__ uint32_t Bs[TK][SROW];   // Bs[k][n]

    int t = threadIdx.x;
    int lane = t & 31;
    int warp = t >> 5;
    int wm = warp >> 2;
    int wn = warp & 3;
    int g  = lane >> 2;
    int tg = lane & 3;

    int rowBlock = blockIdx.y * TM;
    int colBlock = blockIdx.x * TN;

    float c[4][4][4];
    #pragma unroll
    for (int i = 0; i < 4; ++i)
        #pragma unroll
        for (int j = 0; j < 4; ++j)
            #pragma unroll
            for (int k = 0; k < 4; ++k) c[i][j][k] = 0.f;

    for (int k0 = 0; k0 < K; k0 += TK) {
        // A tile: TM x TK = 4096 floats = 1024 float4; 4 per thread.
        // R5-proven mapping: ar = lin>>3 (0..127), ac = (lin&7)<<2 (0..28).
        #pragma unroll
        for (int l = 0; l < 4; ++l) {
            int lin = t + l * 256;
            int ar = lin >> 3;            // 0..127 (m)
            int ac = (lin & 7) << 2;      // 0,4,...,28 (k)
            float4 v = make_float4(0.f, 0.f, 0.f, 0.f);
            int grow = rowBlock + ar;
            if (grow < M)
                v = *(const float4*)&A[(size_t)grow * K + k0 + ac];
            As[ac + 0][ar] = f2tf32(v.x);
            As[ac + 1][ar] = f2tf32(v.y);
            As[ac + 2][ar] = f2tf32(v.z);
            As[ac + 3][ar] = f2tf32(v.w);
        }
        #pragma unroll
        for (int l = 0; l < 4; ++l) {
            int lin = t + l * 256;
            int br = lin >> 5;            // 0..31 (k)
            int bc = (lin & 31) << 2;     // 0..124 (n)
            float4 v = *(const float4*)&B[(size_t)(k0 + br) * NC + colBlock + bc];
            uint4 u;
            u.x = f2tf32(v.x); u.y = f2tf32(v.y);
            u.z = f2tf32(v.z); u.w = f2tf32(v.w);
            *(uint4*)&Bs[br][bc] = u;
        }
        __syncthreads();

        #pragma unroll
        for (int ks = 0; ks < 4; ++ks) {
            int kr = ks * 8 + tg;
            uint32_t a[4][4], b[4][2];
            #pragma unroll
            for (int mt = 0; mt < 4; ++mt) {
                int mb = wm * 64 + mt * 16 + g;
                a[mt][0] = As[kr][mb];
                a[mt][1] = As[kr][mb + 8];
                a[mt][2] = As[kr + 4][mb];
                a[mt][3] = As[kr + 4][mb + 8];
            }
            #pragma unroll
            for (int nt = 0; nt < 4; ++nt) {
                int nb = wn * 32 + nt * 8 + g;
                b[nt][0] = Bs[kr][nb];
                b[nt][1] = Bs[kr + 4][nb];
            }
            #pragma unroll
            for (int mt = 0; mt < 4; ++mt)
                #pragma unroll
                for (int nt = 0; nt < 4; ++nt)
                    mma_tf32(c[mt][nt], a[mt][0], a[mt][1], a[mt][2], a[mt][3],
                             b[nt][0], b[nt][1]);
        }
        __syncthreads();
    }

    #pragma unroll
    for (int mt = 0; mt < 4; ++mt) {
        #pragma unroll
        for (int nt = 0; nt < 4; ++nt) {
            int col = colBlock + wn * 32 + nt * 8 + tg * 2;
            float b0 = 0.f, b1 = 0.f;
            if (bias) { b0 = bias[col]; b1 = bias[col + 1]; }
            int row0 = rowBlock + wm * 64 + mt * 16 + g;
            if (row0 < M) {
                float2 o = make_float2(c[mt][nt][0] + b0, c[mt][nt][1] + b1);
                *(float2*)&C[(size_t)row0 * NC + col] = o;
            }
            int row1 = row0 + 8;
            if (row1 < M) {
                float2 o = make_float2(c[mt][nt][2] + b0, c[mt][nt][3] + b1);
                *(float2*)&C[(size_t)row1 * NC + col] = o;
            }
        }
    }
}

__global__ __launch_bounds__(256) void gemm_xw_kernel(
    const float* __restrict__ A, const float* __restrict__ B, int M) {
    gemm_tf32_core(A, B, nullptr, g_h0, M, F_IN, HDIM);
}

__global__ __launch_bounds__(256) void gemm_proj_kernel(int M) {
    gemm_tf32_core(g_h, g_Wcat, g_bcat, g_P, M, HDIM, PDIM);
}

// ---------------------------------------------------------------------------
// GCN aggregate: one warp per node, unroll 2 edges for MLP.
// ---------------------------------------------------------------------------
__global__ void gcn_agg_kernel(const float* __restrict__ bias, int n) {
    int warp = (blockIdx.x * blockDim.x + threadIdx.x) >> 5;
    int lane = threadIdx.x & 31;
    if (warp >= n) return;
    int i = warp;
    float di = g_dinv[i];

    float4 acc = make_float4(0.f, 0.f, 0.f, 0.f);
    int e0 = g_rowptr[i], e1 = g_rowptr[i + 1];
    int e = e0;
    for (; e + 2 <= e1; e += 2) {
        int s0 = g_csr_src[e];
        int s1 = g_csr_src[e + 1];
        float w0 = g_dinv[s0] * di;
        float w1 = g_dinv[s1] * di;
        float4 v0 = *(const float4*)&g_h0[(size_t)s0 * HDIM + lane * 4];
        float4 v1 = *(const float4*)&g_h0[(size_t)s1 * HDIM + lane * 4];
        acc.x = fmaf(w0, v0.x, acc.x); acc.y = fmaf(w0, v0.y, acc.y);
        acc.z = fmaf(w0, v0.z, acc.z); acc.w = fmaf(w0, v0.w, acc.w);
        acc.x = fmaf(w1, v1.x, acc.x); acc.y = fmaf(w1, v1.y, acc.y);
        acc.z = fmaf(w1, v1.z, acc.z); acc.w = fmaf(w1, v1.w, acc.w);
    }
    if (e < e1) {
        int s0 = g_csr_src[e];
        float w0 = g_dinv[s0] * di;
        float4 v0 = *(const float4*)&g_h0[(size_t)s0 * HDIM + lane * 4];
        acc.x = fmaf(w0, v0.x, acc.x); acc.y = fmaf(w0, v0.y, acc.y);
        acc.z = fmaf(w0, v0.z, acc.z); acc.w = fmaf(w0, v0.w, acc.w);
    }
    {   // self loop
        float w = di * di;
        float4 v = *(const float4*)&g_h0[(size_t)i * HDIM + lane * 4];
        acc.x = fmaf(w, v.x, acc.x); acc.y = fmaf(w, v.y, acc.y);
        acc.z = fmaf(w, v.z, acc.z); acc.w = fmaf(w, v.w, acc.w);
    }
    float4 bb = *(const float4*)&bias[lane * 4];
    acc.x += bb.x; acc.y += bb.y; acc.z += bb.z; acc.w += bb.w;
    acc.x = (acc.x >= 0.f) ? acc.x : 0.01f * acc.x;
    acc.y = (acc.y >= 0.f) ? acc.y : 0.01f * acc.y;
    acc.z = (acc.z >= 0.f) ? acc.z : 0.01f * acc.z;
    acc.w = (acc.w >= 0.f) ? acc.w : 0.01f * acc.w;
    *(float4*)&g_h[(size_t)i * HDIM + lane * 4] = acc;
}

// ---------------------------------------------------------------------------
// Fused TransformerConv (mu + logstd): one warp per dst node, online softmax.
// Interleaved P layout: lane l's float2 at word 2l of a block = dims (l, l+32).
// Unroll 2 edges.
// ---------------------------------------------------------------------------
struct EdgeData {
    float2 km, kl, vm, vl;
};

__device__ __forceinline__ EdgeData load_edge(int src, int lane) {
    const float2* Ps2 = (const float2*)&g_P[(size_t)src * PDIM];
    EdgeData d;
    d.km = Ps2[(OFF_KMU >> 1) + lane];
    d.kl = Ps2[(OFF_KLS >> 1) + lane];
    d.vm = Ps2[(OFF_VMU >> 1) + lane];
    d.vl = Ps2[(OFF_VLS >> 1) + lane];
    return d;
}

__global__ void transformer_kernel(float* __restrict__ out, int n) {
    int warp = (blockIdx.x * blockDim.x + threadIdx.x) >> 5;
    int lane = threadIdx.x & 31;
    if (warp >= n) return;
    int i = warp;
    const float2* Pi2 = (const float2*)&g_P[(size_t)i * PDIM];

    float2 qm = Pi2[(OFF_QMU >> 1) + lane];
    float2 ql = Pi2[(OFF_QLS >> 1) + lane];

    float mm = -INFINITY, ml = -INFINITY;
    float sm = 0.f, sl = 0.f;
    float2 am = make_float2(0.f, 0.f);
    float2 al = make_float2(0.f, 0.f);

    int e0 = g_rowptr[i], e1 = g_rowptr[i + 1];
    int e = e0;
    for (; e + 2 <= e1; e += 2) {
        int s0 = g_csr_src[e];
        int s1 = g_csr_src[e + 1];
        EdgeData d0 = load_edge(s0, lane);
        EdgeData d1 = load_edge(s1, lane);

        float pm0 = qm.x * d0.km.x + qm.y * d0.km.y;
        float pl0 = ql.x * d0.kl.x + ql.y * d0.kl.y;
        float pm1 = qm.x * d1.km.x + qm.y * d1.km.y;
        float pl1 = ql.x * d1.kl.x + ql.y * d1.kl.y;
        #pragma unroll
        for (int off = 16; off; off >>= 1) {
            pm0 += __shfl_xor_sync(0xffffffffu, pm0, off);
            pl0 += __shfl_xor_sync(0xffffffffu, pl0, off);
            pm1 += __shfl_xor_sync(0xffffffffu, pm1, off);
            pl1 += __shfl_xor_sync(0xffffffffu, pl1, off);
        }
        float alm0 = pm0 * 0.125f, all0 = pl0 * 0.125f;
        float alm1 = pm1 * 0.125f, all1 = pl1 * 0.125f;

        {   // mu edge 0
            float nm = fmaxf(mm, alm0);
            float scale = __expf(mm - nm);
            float p = __expf(alm0 - nm);
            sm = sm * scale + p;
            am.x = am.x * scale + p * d0.vm.x;
            am.y = am.y * scale + p * d0.vm.y;
            mm = nm;
        }
        {   // mu edge 1
            float nm = fmaxf(mm, alm1);
            float scale = __expf(mm - nm);
            float p = __expf(alm1 - nm);
            sm = sm * scale + p;
            am.x = am.x * scale + p * d1.vm.x;
            am.y = am.y * scale + p * d1.vm.y;
            mm = nm;
        }
        {   // ls edge 0
            float nm = fmaxf(ml, all0);
            float scale = __expf(ml - nm);
            float p = __expf(all0 - nm);
            sl = sl * scale + p;
            al.x = al.x * scale + p * d0.vl.x;
            al.y = al.y * scale + p * d0.vl.y;
            ml = nm;
        }
        {   // ls edge 1
            float nm = fmaxf(ml, all1);
            float scale = __expf(ml - nm);
            float p = __expf(all1 - nm);
            sl = sl * scale + p;
            al.x = al.x * scale + p * d1.vl.x;
            al.y = al.y * scale + p * d1.vl.y;
            ml = nm;
        }
    }
    if (e < e1) {
        int s0 = g_csr_src[e];
        EdgeData d0 = load_edge(s0, lane);
        float pm0 = qm.x * d0.km.x + qm.y * d0.km.y;
        float pl0 = ql.x * d0.kl.x + ql.y * d0.kl.y;
        #pragma unroll
        for (int off = 16; off; off >>= 1) {
            pm0 += __shfl_xor_sync(0xffffffffu, pm0, off);
            pl0 += __shfl_xor_sync(0xffffffffu, pl0, off);
        }
        float alm0 = pm0 * 0.125f, all0 = pl0 * 0.125f;
        {
            float nm = fmaxf(mm, alm0);
            float scale = __expf(mm - nm);
            float p = __expf(alm0 - nm);
            sm = sm * scale + p;
            am.x = am.x * scale + p * d0.vm.x;
            am.y = am.y * scale + p * d0.vm.y;
            mm = nm;
        }
        {
            float nm = fmaxf(ml, all0);
            float scale = __expf(ml - nm);
            float p = __expf(all0 - nm);
            sl = sl * scale + p;
            al.x = al.x * scale + p * d0.vl.x;
            al.y = al.y * scale + p * d0.vl.y;
            ml = nm;
        }
    }

    // lane l holds output dims (l, l+32) of both mu and logstd.
    float2 smu = Pi2[(OFF_SMU >> 1) + lane];
    float2 sls = Pi2[(OFF_SLS >> 1) + lane];
    size_t nd = (size_t)n * DDIM;
    float rm = 1.0f / (sm + 1e-16f);
    float rl = 1.0f / (sl + 1e-16f);
    out[(size_t)i * DDIM + lane]      = am.x * rm + smu.x;
    out[(size_t)i * DDIM + 32 + lane] = am.y * rm + smu.y;
    out[nd + (size_t)i * DDIM + lane]      = fminf(al.x * rl + sls.x, 10.0f);
    out[nd + (size_t)i * DDIM + 32 + lane] = fminf(al.y * rl + sls.y, 10.0f);
}

// ---------------------------------------------------------------------------
// Launch
// ---------------------------------------------------------------------------
extern "C" void kernel_launch(void* const* d_in, const int* in_sizes, int n_in,
                              void* d_out, int out_size) {
    const float* x     = (const float*)d_in[0];
    const void*  ei    = (const void*)d_in[1];
    const float* W_gcn = (const float*)d_in[2];
    const float* b_gcn = (const float*)d_in[3];
    const float* Wq_mu = (const float*)d_in[4];  const float* bq_mu = (const float*)d_in[5];
    const float* Wk_mu = (const float*)d_in[6];  const float* bk_mu = (const float*)d_in[7];
    const float* Wv_mu = (const float*)d_in[8];  const float* bv_mu = (const float*)d_in[9];
    const float* Ws_mu = (const float*)d_in[10]; const float* bs_mu = (const float*)d_in[11];
    const float* Wq_ls = (const float*)d_in[12]; const float* bq_ls = (const float*)d_in[13];
    const float* Wk_ls = (const float*)d_in[14]; const float* bk_ls = (const float*)d_in[15];
    const float* Wv_ls = (const float*)d_in[16]; const float* bv_ls = (const float*)d_in[17];
    const float* Ws_ls = (const float*)d_in[18]; const float* bs_ls = (const float*)d_in[19];
    float* out = (float*)d_out;

    int n = in_sizes[0] / F_IN;      // 50000
    int e = in_sizes[1] / 2;         // 800000

    // 0) dtype detect
    detect_dtype_kernel<<<1, 256>>>((const int*)ei, e);

    // 1) CSR build
    zero_cnt_kernel<<<(n + 255) / 256, 256>>>(n);
    edge_prep_kernel<<<(e + 255) / 256, 256>>>(ei, e, n);
    int nblk = (n + 1023) / 1024;
    scan_pass1_kernel<<<nblk, 1024>>>(n);
    scan_pass2_kernel<<<nblk, 1024>>>(n);
    fill_csr_kernel<<<(e + 255) / 256, 256>>>(e);

    // 2) Pack projection weights (interleaved dims)
    pack_weights_kernel<<<(HDIM * PDIM + 255) / 256, 256>>>(
        Wq_mu, Ws_mu, Wq_ls, Ws_ls, Wk_mu, Wv_mu, Wk_ls, Wv_ls,
        bq_mu, bs_mu, bq_ls, bs_ls, bk_mu, bv_mu, bk_ls, bv_ls);

    // 3) h0 = x @ W_gcn    [n,256]@[256,128]  (tf32 MMA, R5 engine)
    {
        dim3 grid(HDIM / TN, (n + TM - 1) / TM);
        gemm_xw_kernel<<<grid, 256>>>(x, W_gcn, n);
    }

    // 4) GCN aggregate + bias + LeakyReLU -> h
    gcn_agg_kernel<<<(n + 7) / 8, 256>>>(b_gcn, n);

    // 5) P = h @ Wcat + bcat    [n,128]@[128,512]  (tf32 MMA, R5 engine)
    {
        dim3 grid(PDIM / TN, (n + TM - 1) / TM);
        gemm_proj_kernel<<<grid, 256>>>(n);
    }

    // 6) Fused TransformerConv (mu + logstd) -> out
    transformer_kernel<<<(n + 7) / 8, 256>>>(out, n);
}

// round 10
// speedup vs baseline: 1.4463x; 1.0887x over previous
#include <cuda_runtime.h>
#include <cuda_bf16.h>
#include <math.h>
#include <stdint.h>

// ---------------------------------------------------------------------------
// Problem constants
// ---------------------------------------------------------------------------
#define NMAX 50000
#define EMAX 800000
#define F_IN 256
#define HDIM 128
#define DDIM 64
#define PDIM 512   // 8 projections x 64

// Packed projection block offsets within a row of P.
// Within each 64-dim block, dim c lives at position 2*(c%32) + (c/32):
// lane l reads the float2 at word 2l = dims (l, l+32).
#define OFF_QMU 0
#define OFF_SMU 64
#define OFF_QLS 128
#define OFF_SLS 192
#define OFF_KMU 256
#define OFF_VMU 320
#define OFF_KLS 384
#define OFF_VLS 448

// ---------------------------------------------------------------------------
// Static device scratch
// ---------------------------------------------------------------------------
__device__ int   g_is64;
__device__ int   g_cnt[NMAX];
__device__ int   g_pref[NMAX];
__device__ int   g_bsum[64];
__device__ int   g_rowptr[NMAX + 1];
__device__ int   g_cursor[NMAX];
__device__ int   g_src32[EMAX];
__device__ int   g_dst32[EMAX];
__device__ int   g_csr_src[EMAX];
__device__ float g_dinv[NMAX];
__device__ float g_h0[(size_t)NMAX * HDIM];   // x @ W_gcn
__device__ float g_h [(size_t)NMAX * HDIM];   // after agg + bias + leaky
__device__ float g_P [(size_t)NMAX * PDIM];   // packed projections (interleaved)
__device__ float g_Wcat[HDIM * PDIM];
__device__ float g_bcat[PDIM];

// ---------------------------------------------------------------------------
// Edge dtype detection
// ---------------------------------------------------------------------------
__global__ void detect_dtype_kernel(const int* __restrict__ w, int e) {
    __shared__ int s[256];
    int t = threadIdx.x;
    int limit = (e < 256) ? e : 256;
    int nz = 0;
    if (t < limit) nz = (w[2 * t + 1] != 0) ? 1 : 0;
    s[t] = nz;
    __syncthreads();
    for (int o = 128; o; o >>= 1) {
        if (t < o) s[t] += s[t + o];
        __syncthreads();
    }
    if (t == 0) g_is64 = (s[0] == 0) ? 1 : 0;
}

__global__ void zero_cnt_kernel(int n) {
    int i = blockIdx.x * blockDim.x + threadIdx.x;
    if (i < n) g_cnt[i] = 0;
}

__global__ void edge_prep_kernel(const void* __restrict__ ei, int e, int n) {
    int idx = blockIdx.x * blockDim.x + threadIdx.x;
    if (idx >= e) return;
    int s, d;
    if (g_is64) {
        const long long* p = (const long long*)ei;
        s = (int)p[idx];
        d = (int)p[idx + e];
    } else {
        const int* p = (const int*)ei;
        s = p[idx];
        d = p[idx + e];
    }
    s = (s < 0) ? 0 : ((s >= n) ? n - 1 : s);
    d = (d < 0) ? 0 : ((d >= n) ? n - 1 : d);
    g_src32[idx] = s;
    g_dst32[idx] = d;
    atomicAdd(&g_cnt[d], 1);
}

// ---------------------------------------------------------------------------
// Parallel scan (2 passes)
// ---------------------------------------------------------------------------
__global__ void scan_pass1_kernel(int n) {
    __shared__ int s[1024];
    int t = threadIdx.x;
    int i = blockIdx.x * 1024 + t;
    int v = (i < n) ? g_cnt[i] : 0;
    s[t] = v;
    __syncthreads();
    #pragma unroll
    for (int off = 1; off < 1024; off <<= 1) {
        int u = 0;
        if (t >= off) u = s[t - off];
        __syncthreads();
        if (t >= off) s[t] += u;
        __syncthreads();
    }
    if (i < n) g_pref[i] = s[t];
    if (t == 1023) g_bsum[blockIdx.x] = s[t];
}

__global__ void scan_pass2_kernel(int n) {
    __shared__ int sboff;
    int b = blockIdx.x;
    int t = threadIdx.x;
    if (t == 0) {
        int acc = 0;
        for (int j = 0; j < b; ++j) acc += g_bsum[j];
        sboff = acc;
    }
    __syncthreads();
    int i = b * 1024 + t;
    if (i < n) {
        int incl = g_pref[i] + sboff;
        int c = g_cnt[i];
        int excl = incl - c;
        g_rowptr[i] = excl;
        g_cursor[i] = excl;
        g_dinv[i] = rsqrtf((float)(c + 1));
        if (i == n - 1) g_rowptr[n] = incl;
    }
}

__global__ void fill_csr_kernel(int e) {
    int idx = blockIdx.x * blockDim.x + threadIdx.x;
    if (idx >= e) return;
    int d = g_dst32[idx];
    int pos = atomicAdd(&g_cursor[d], 1);
    g_csr_src[pos] = g_src32[idx];
}

// Pointer order matches packed offsets: qmu,smu,qls,sls,kmu,vmu,kls,vls.
// Within each 64-wide block, packed position cp holds original col
// c = (cp>>1) + 32*(cp&1).
__global__ void pack_weights_kernel(
    const float* W0, const float* W1, const float* W2, const float* W3,
    const float* W4, const float* W5, const float* W6, const float* W7,
    const float* b0, const float* b1, const float* b2, const float* b3,
    const float* b4, const float* b5, const float* b6, const float* b7) {
    const float* Ws[8] = {W0, W1, W2, W3, W4, W5, W6, W7};
    const float* bs[8] = {b0, b1, b2, b3, b4, b5, b6, b7};
    int idx = blockIdx.x * blockDim.x + threadIdx.x;
    if (idx < HDIM * PDIM) {
        int k = idx / PDIM;
        int j = idx % PDIM;
        int p = j / DDIM;
        int cp = j % DDIM;
        int c = (cp >> 1) + 32 * (cp & 1);
        g_Wcat[idx] = Ws[p][k * DDIM + c];
    }
    if (idx < PDIM) {
        int p = idx / DDIM;
        int cp = idx % DDIM;
        int c = (cp >> 1) + 32 * (cp & 1);
        g_bcat[idx] = bs[p][c];
    }
}

// ---------------------------------------------------------------------------
// TF32 tensor-core GEMM (R5 engine + pair-interleaved A columns so each MMA
// a-fragment (m, m+8) pair is one conflict-free LDS.64).
// Block 128x128x32, 256 threads = 8 warps (2x4), warp tile 64x32.
// ---------------------------------------------------------------------------
#define TM 128
#define TN 128
#define TK 32
#define SROW 136

__device__ __forceinline__ uint32_t f2tf32(float v) {
    uint32_t o;
    asm volatile("cvt.rna.tf32.f32 %0, %1;" : "=r"(o) : "f"(v));
    return o;
}

// column permutation: (m, m+8) adjacent within each 16-row group
__device__ __forceinline__ int a_colp(int m) {
    return ((m >> 4) << 4) + ((m & 7) << 1) + ((m >> 3) & 1);
}

__device__ __forceinline__ void mma_tf32(float* c,
    uint32_t a0, uint32_t a1, uint32_t a2, uint32_t a3,
    uint32_t b0, uint32_t b1) {
    asm volatile(
        "mma.sync.aligned.m16n8k8.row.col.f32.tf32.tf32.f32 "
        "{%0,%1,%2,%3}, {%4,%5,%6,%7}, {%8,%9}, {%0,%1,%2,%3};"
        : "+f"(c[0]), "+f"(c[1]), "+f"(c[2]), "+f"(c[3])
        : "r"(a0), "r"(a1), "r"(a2), "r"(a3), "r"(b0), "r"(b1));
}

__device__ __forceinline__ void gemm_tf32_core(
    const float* __restrict__ A, const float* __restrict__ B,
    const float* __restrict__ bias, float* __restrict__ C,
    int M, int K, int NC) {
    __shared__ __align__(16) uint32_t As[TK][SROW];   // As[k][colp(m)]
    __shared__ __align__(16) uint32_t Bs[TK][SROW];   // Bs[k][n]

    int t = threadIdx.x;
    int lane = t & 31;
    int warp = t >> 5;
    int wm = warp >> 2;
    int wn = warp & 3;
    int g  = lane >> 2;
    int tg = lane & 3;

    int rowBlock = blockIdx.y * TM;
    int colBlock = blockIdx.x * TN;

    float c[4][4][4];
    #pragma unroll
    for (int i = 0; i < 4; ++i)
        #pragma unroll
        for (int j = 0; j < 4; ++j)
            #pragma unroll
            for (int k = 0; k < 4; ++k) c[i][j][k] = 0.f;

    for (int k0 = 0; k0 < K; k0 += TK) {
        // A tile: TM x TK = 1024 float4; 4 per thread (R5-proven mapping),
        // stored to permuted column colp(ar).
        #pragma unroll
        for (int l = 0; l < 4; ++l) {
            int lin = t + l * 256;
            int ar = lin >> 3;            // 0..127 (m)
            int ac = (lin & 7) << 2;      // 0,4,...,28 (k)
            float4 v = make_float4(0.f, 0.f, 0.f, 0.f);
            int grow = rowBlock + ar;
            if (grow < M)
                v = *(const float4*)&A[(size_t)grow * K + k0 + ac];
            int cp = a_colp(ar);
            As[ac + 0][cp] = f2tf32(v.x);
            As[ac + 1][cp] = f2tf32(v.y);
            As[ac + 2][cp] = f2tf32(v.z);
            As[ac + 3][cp] = f2tf32(v.w);
        }
        #pragma unroll
        for (int l = 0; l < 4; ++l) {
            int lin = t + l * 256;
            int br = lin >> 5;            // 0..31 (k)
            int bc = (lin & 31) << 2;     // 0..124 (n)
            float4 v = *(const float4*)&B[(size_t)(k0 + br) * NC + colBlock + bc];
            uint4 u;
            u.x = f2tf32(v.x); u.y = f2tf32(v.y);
            u.z = f2tf32(v.z); u.w = f2tf32(v.w);
            *(uint4*)&Bs[br][bc] = u;
        }
        __syncthreads();

        #pragma unroll
        for (int ks = 0; ks < 4; ++ks) {
            int kr = ks * 8 + tg;
            uint32_t a[4][4], b[4][2];
            #pragma unroll
            for (int mt = 0; mt < 4; ++mt) {
                int pcol = (wm * 4 + mt) * 16 + (g << 1);
                uint2 p0 = *(const uint2*)&As[kr][pcol];
                uint2 p1 = *(const uint2*)&As[kr + 4][pcol];
                a[mt][0] = p0.x; a[mt][1] = p0.y;
                a[mt][2] = p1.x; a[mt][3] = p1.y;
            }
            #pragma unroll
            for (int nt = 0; nt < 4; ++nt) {
                int nb = wn * 32 + nt * 8 + g;
                b[nt][0] = Bs[kr][nb];
                b[nt][1] = Bs[kr + 4][nb];
            }
            #pragma unroll
            for (int mt = 0; mt < 4; ++mt)
                #pragma unroll
                for (int nt = 0; nt < 4; ++nt)
                    mma_tf32(c[mt][nt], a[mt][0], a[mt][1], a[mt][2], a[mt][3],
                             b[nt][0], b[nt][1]);
        }
        __syncthreads();
    }

    #pragma unroll
    for (int mt = 0; mt < 4; ++mt) {
        #pragma unroll
        for (int nt = 0; nt < 4; ++nt) {
            int col = colBlock + wn * 32 + nt * 8 + tg * 2;
            float b0 = 0.f, b1 = 0.f;
            if (bias) { b0 = bias[col]; b1 = bias[col + 1]; }
            int row0 = rowBlock + wm * 64 + mt * 16 + g;
            if (row0 < M) {
                float2 o = make_float2(c[mt][nt][0] + b0, c[mt][nt][1] + b1);
                *(float2*)&C[(size_t)row0 * NC + col] = o;
            }
            int row1 = row0 + 8;
            if (row1 < M) {
                float2 o = make_float2(c[mt][nt][2] + b0, c[mt][nt][3] + b1);
                *(float2*)&C[(size_t)row1 * NC + col] = o;
            }
        }
    }
}

__global__ __launch_bounds__(256) void gemm_xw_kernel(
    const float* __restrict__ A, const float* __restrict__ B, int M) {
    gemm_tf32_core(A, B, nullptr, g_h0, M, F_IN, HDIM);
}

__global__ __launch_bounds__(256) void gemm_proj_kernel(int M) {
    gemm_tf32_core(g_h, g_Wcat, g_bcat, g_P, M, HDIM, PDIM);
}

// ---------------------------------------------------------------------------
// GCN aggregate: one warp per node, unroll 2 edges for MLP.
// ---------------------------------------------------------------------------
__global__ void gcn_agg_kernel(const float* __restrict__ bias, int n) {
    int warp = (blockIdx.x * blockDim.x + threadIdx.x) >> 5;
    int lane = threadIdx.x & 31;
    if (warp >= n) return;
    int i = warp;
    float di = g_dinv[i];

    float4 acc = make_float4(0.f, 0.f, 0.f, 0.f);
    int e0 = g_rowptr[i], e1 = g_rowptr[i + 1];
    int e = e0;
    for (; e + 2 <= e1; e += 2) {
        int s0 = g_csr_src[e];
        int s1 = g_csr_src[e + 1];
        float w0 = g_dinv[s0] * di;
        float w1 = g_dinv[s1] * di;
        float4 v0 = *(const float4*)&g_h0[(size_t)s0 * HDIM + lane * 4];
        float4 v1 = *(const float4*)&g_h0[(size_t)s1 * HDIM + lane * 4];
        acc.x = fmaf(w0, v0.x, acc.x); acc.y = fmaf(w0, v0.y, acc.y);
        acc.z = fmaf(w0, v0.z, acc.z); acc.w = fmaf(w0, v0.w, acc.w);
        acc.x = fmaf(w1, v1.x, acc.x); acc.y = fmaf(w1, v1.y, acc.y);
        acc.z = fmaf(w1, v1.z, acc.z); acc.w = fmaf(w1, v1.w, acc.w);
    }
    if (e < e1) {
        int s0 = g_csr_src[e];
        float w0 = g_dinv[s0] * di;
        float4 v0 = *(const float4*)&g_h0[(size_t)s0 * HDIM + lane * 4];
        acc.x = fmaf(w0, v0.x, acc.x); acc.y = fmaf(w0, v0.y, acc.y);
        acc.z = fmaf(w0, v0.z, acc.z); acc.w = fmaf(w0, v0.w, acc.w);
    }
    {   // self loop
        float w = di * di;
        float4 v = *(const float4*)&g_h0[(size_t)i * HDIM + lane * 4];
        acc.x = fmaf(w, v.x, acc.x); acc.y = fmaf(w, v.y, acc.y);
        acc.z = fmaf(w, v.z, acc.z); acc.w = fmaf(w, v.w, acc.w);
    }
    float4 bb = *(const float4*)&bias[lane * 4];
    acc.x += bb.x; acc.y += bb.y; acc.z += bb.z; acc.w += bb.w;
    acc.x = (acc.x >= 0.f) ? acc.x : 0.01f * acc.x;
    acc.y = (acc.y >= 0.f) ? acc.y : 0.01f * acc.y;
    acc.z = (acc.z >= 0.f) ? acc.z : 0.01f * acc.z;
    acc.w = (acc.w >= 0.f) ? acc.w : 0.01f * acc.w;
    *(float4*)&g_h[(size_t)i * HDIM + lane * 4] = acc;
}

// ---------------------------------------------------------------------------
// Fused TransformerConv (mu + logstd): one warp per dst node, online softmax.
// Interleaved P layout: lane l's float2 at word 2l of a block = dims (l, l+32).
// Unroll 2 edges.
// ---------------------------------------------------------------------------
struct EdgeData {
    float2 km, kl, vm, vl;
};

__device__ __forceinline__ EdgeData load_edge(int src, int lane) {
    const float2* Ps2 = (const float2*)&g_P[(size_t)src * PDIM];
    EdgeData d;
    d.km = Ps2[(OFF_KMU >> 1) + lane];
    d.kl = Ps2[(OFF_KLS >> 1) + lane];
    d.vm = Ps2[(OFF_VMU >> 1) + lane];
    d.vl = Ps2[(OFF_VLS >> 1) + lane];
    return d;
}

__global__ void transformer_kernel(float* __restrict__ out, int n) {
    int warp = (blockIdx.x * blockDim.x + threadIdx.x) >> 5;
    int lane = threadIdx.x & 31;
    if (warp >= n) return;
    int i = warp;
    const float2* Pi2 = (const float2*)&g_P[(size_t)i * PDIM];

    float2 qm = Pi2[(OFF_QMU >> 1) + lane];
    float2 ql = Pi2[(OFF_QLS >> 1) + lane];

    float mm = -INFINITY, ml = -INFINITY;
    float sm = 0.f, sl = 0.f;
    float2 am = make_float2(0.f, 0.f);
    float2 al = make_float2(0.f, 0.f);

    int e0 = g_rowptr[i], e1 = g_rowptr[i + 1];
    int e = e0;
    for (; e + 2 <= e1; e += 2) {
        int s0 = g_csr_src[e];
        int s1 = g_csr_src[e + 1];
        EdgeData d0 = load_edge(s0, lane);
        EdgeData d1 = load_edge(s1, lane);

        float pm0 = qm.x * d0.km.x + qm.y * d0.km.y;
        float pl0 = ql.x * d0.kl.x + ql.y * d0.kl.y;
        float pm1 = qm.x * d1.km.x + qm.y * d1.km.y;
        float pl1 = ql.x * d1.kl.x + ql.y * d1.kl.y;
        #pragma unroll
        for (int off = 16; off; off >>= 1) {
            pm0 += __shfl_xor_sync(0xffffffffu, pm0, off);
            pl0 += __shfl_xor_sync(0xffffffffu, pl0, off);
            pm1 += __shfl_xor_sync(0xffffffffu, pm1, off);
            pl1 += __shfl_xor_sync(0xffffffffu, pl1, off);
        }
        float alm0 = pm0 * 0.125f, all0 = pl0 * 0.125f;
        float alm1 = pm1 * 0.125f, all1 = pl1 * 0.125f;

        {   // mu edge 0
            float nm = fmaxf(mm, alm0);
            float scale = __expf(mm - nm);
            float p = __expf(alm0 - nm);
            sm = sm * scale + p;
            am.x = am.x * scale + p * d0.vm.x;
            am.y = am.y * scale + p * d0.vm.y;
            mm = nm;
        }
        {   // mu edge 1
            float nm = fmaxf(mm, alm1);
            float scale = __expf(mm - nm);
            float p = __expf(alm1 - nm);
            sm = sm * scale + p;
            am.x = am.x * scale + p * d1.vm.x;
            am.y = am.y * scale + p * d1.vm.y;
            mm = nm;
        }
        {   // ls edge 0
            float nm = fmaxf(ml, all0);
            float scale = __expf(ml - nm);
            float p = __expf(all0 - nm);
            sl = sl * scale + p;
            al.x = al.x * scale + p * d0.vl.x;
            al.y = al.y * scale + p * d0.vl.y;
            ml = nm;
        }
        {   // ls edge 1
            float nm = fmaxf(ml, all1);
            float scale = __expf(ml - nm);
            float p = __expf(all1 - nm);
            sl = sl * scale + p;
            al.x = al.x * scale + p * d1.vl.x;
            al.y = al.y * scale + p * d1.vl.y;
            ml = nm;
        }
    }
    if (e < e1) {
        int s0 = g_csr_src[e];
        EdgeData d0 = load_edge(s0, lane);
        float pm0 = qm.x * d0.km.x + qm.y * d0.km.y;
        float pl0 = ql.x * d0.kl.x + ql.y * d0.kl.y;
        #pragma unroll
        for (int off = 16; off; off >>= 1) {
            pm0 += __shfl_xor_sync(0xffffffffu, pm0, off);
            pl0 += __shfl_xor_sync(0xffffffffu, pl0, off);
        }
        float alm0 = pm0 * 0.125f, all0 = pl0 * 0.125f;
        {
            float nm = fmaxf(mm, alm0);
            float scale = __expf(mm - nm);
            float p = __expf(alm0 - nm);
            sm = sm * scale + p;
            am.x = am.x * scale + p * d0.vm.x;
            am.y = am.y * scale + p * d0.vm.y;
            mm = nm;
        }
        {
            float nm = fmaxf(ml, all0);
            float scale = __expf(ml - nm);
            float p = __expf(all0 - nm);
            sl = sl * scale + p;
            al.x = al.x * scale + p * d0.vl.x;
            al.y = al.y * scale + p * d0.vl.y;
            ml = nm;
        }
    }

    // lane l holds output dims (l, l+32) of both mu and logstd.
    float2 smu = Pi2[(OFF_SMU >> 1) + lane];
    float2 sls = Pi2[(OFF_SLS >> 1) + lane];
    size_t nd = (size_t)n * DDIM;
    float rm = 1.0f / (sm + 1e-16f);
    float rl = 1.0f / (sl + 1e-16f);
    out[(size_t)i * DDIM + lane]      = am.x * rm + smu.x;
    out[(size_t)i * DDIM + 32 + lane] = am.y * rm + smu.y;
    out[nd + (size_t)i * DDIM + lane]      = fminf(al.x * rl + sls.x, 10.0f);
    out[nd + (size_t)i * DDIM + 32 + lane] = fminf(al.y * rl + sls.y, 10.0f);
}

// ---------------------------------------------------------------------------
// Launch: fork the CSR/pack prep chain onto a side stream so it overlaps
// with gemm_xw (independent inputs); join before gcn_agg.
// ---------------------------------------------------------------------------
extern "C" void kernel_launch(void* const* d_in, const int* in_sizes, int n_in,
                              void* d_out, int out_size) {
    const float* x     = (const float*)d_in[0];
    const void*  ei    = (const void*)d_in[1];
    const float* W_gcn = (const float*)d_in[2];
    const float* b_gcn = (const float*)d_in[3];
    const float* Wq_mu = (const float*)d_in[4];  const float* bq_mu = (const float*)d_in[5];
    const float* Wk_mu = (const float*)d_in[6];  const float* bk_mu = (const float*)d_in[7];
    const float* Wv_mu = (const float*)d_in[8];  const float* bv_mu = (const float*)d_in[9];
    const float* Ws_mu = (const float*)d_in[10]; const float* bs_mu = (const float*)d_in[11];
    const float* Wq_ls = (const float*)d_in[12]; const float* bq_ls = (const float*)d_in[13];
    const float* Wk_ls = (const float*)d_in[14]; const float* bk_ls = (const float*)d_in[15];
    const float* Wv_ls = (const float*)d_in[16]; const float* bv_ls = (const float*)d_in[17];
    const float* Ws_ls = (const float*)d_in[18]; const float* bs_ls = (const float*)d_in[19];
    float* out = (float*)d_out;

    int n = in_sizes[0] / F_IN;      // 50000
    int e = in_sizes[1] / 2;         // 800000

    // kernel_launch is called only a handful of times (correctness + capture),
    // so per-call stream/event creation is cheap; intentionally not destroyed
    // (destroying while capture is active is the risky path).
    cudaStream_t s2;
    cudaStreamCreate(&s2);
    cudaEvent_t evFork, evJoin;
    cudaEventCreateWithFlags(&evFork, cudaEventDisableTiming);
    cudaEventCreateWithFlags(&evJoin, cudaEventDisableTiming);

    // fork
    cudaEventRecord(evFork, 0);
    cudaStreamWaitEvent(s2, evFork, 0);

    // --- side stream: CSR build + weight pack (independent of gemm_xw) ---
    detect_dtype_kernel<<<1, 256, 0, s2>>>((const int*)ei, e);
    zero_cnt_kernel<<<(n + 255) / 256, 256, 0, s2>>>(n);
    edge_prep_kernel<<<(e + 255) / 256, 256, 0, s2>>>(ei, e, n);
    int nblk = (n + 1023) / 1024;
    scan_pass1_kernel<<<nblk, 1024, 0, s2>>>(n);
    scan_pass2_kernel<<<nblk, 1024, 0, s2>>>(n);
    fill_csr_kernel<<<(e + 255) / 256, 256, 0, s2>>>(e);
    pack_weights_kernel<<<(HDIM * PDIM + 255) / 256, 256, 0, s2>>>(
        Wq_mu, Ws_mu, Wq_ls, Ws_ls, Wk_mu, Wv_mu, Wk_ls, Wv_ls,
        bq_mu, bs_mu, bq_ls, bs_ls, bk_mu, bv_mu, bk_ls, bv_ls);
    cudaEventRecord(evJoin, s2);

    // --- main stream: h0 = x @ W_gcn (needs only x, W_gcn) ---
    {
        dim3 grid(HDIM / TN, (n + TM - 1) / TM);
        gemm_xw_kernel<<<grid, 256>>>(x, W_gcn, n);
    }

    // join
    cudaStreamWaitEvent(0, evJoin, 0);

    // 4) GCN aggregate + bias + LeakyReLU -> h
    gcn_agg_kernel<<<(n + 7) / 8, 256>>>(b_gcn, n);

    // 5) P = h @ Wcat + bcat    [n,128]@[128,512]
    {
        dim3 grid(PDIM / TN, (n + TM - 1) / TM);
        gemm_proj_kernel<<<grid, 256>>>(n);
    }

    // 6) Fused TransformerConv (mu + logstd) -> out
    transformer_kernel<<<(n + 7) / 8, 256>>>(out, n);
}